// round 1
// baseline (speedup 1.0000x reference)
#include <cuda_runtime.h>
#include <math.h>

#define D 128
#define NRELS 16
#define MAXN 50000

// Scratch (allocation-free rule: __device__ globals)
__device__ float g_hall[(size_t)NRELS * MAXN * D];   // [r][n][d] transformed features
__device__ float g_glog[(size_t)MAXN * NRELS];       // [n][r] gate logits
__device__ float g_h1[(size_t)MAXN * D];             // layer-0 output

// ---------------------------------------------------------------------------
// Register-tiled SGEMM: C[z] = A @ B[z] (+bias). A:[M x 128], B:[128 x 128]
// BM=BN=128, BK=8, 256 threads, 8x8 per thread.
// ---------------------------------------------------------------------------
__global__ __launch_bounds__(256, 2)
void sgemm_kernel(const float* __restrict__ A, const float* __restrict__ B0,
                  float* __restrict__ C0, int M, const float* __restrict__ bias)
{
    const int z = blockIdx.z;
    const float* B = B0 + (size_t)z * D * D;
    float* C = C0 + (size_t)z * (size_t)M * D;

    __shared__ float As[8][128];   // transposed A tile
    __shared__ float Bs[8][128];

    const int tid  = threadIdx.x;
    const int trow = tid / 16;          // 0..15 (M direction)
    const int tcol = tid % 16;          // 0..15 (N direction)

    const int rowBase = blockIdx.x * 128;

    const int aRow = tid >> 1;          // 0..127
    const int aCol = (tid & 1) * 4;     // 0 or 4
    const int bRow = tid >> 5;          // 0..7
    const int bCol = (tid & 31) * 4;    // 0..124

    float acc[8][8];
#pragma unroll
    for (int i = 0; i < 8; i++)
#pragma unroll
        for (int j = 0; j < 8; j++) acc[i][j] = 0.f;

    const int gRowA = rowBase + aRow;
    const bool aValid = (gRowA < M);
    const float* Aptr = A + (size_t)(aValid ? gRowA : 0) * D + aCol;

    for (int k0 = 0; k0 < D; k0 += 8) {
        float4 av = make_float4(0.f, 0.f, 0.f, 0.f);
        if (aValid) av = *(const float4*)(Aptr + k0);
        As[aCol + 0][aRow] = av.x;
        As[aCol + 1][aRow] = av.y;
        As[aCol + 2][aRow] = av.z;
        As[aCol + 3][aRow] = av.w;
        *(float4*)(&Bs[bRow][bCol]) =
            *(const float4*)(B + (size_t)(k0 + bRow) * D + bCol);
        __syncthreads();
#pragma unroll
        for (int k = 0; k < 8; k++) {
            float a_reg[8], b_reg[8];
#pragma unroll
            for (int i = 0; i < 8; i++) a_reg[i] = As[k][trow * 8 + i];
#pragma unroll
            for (int j = 0; j < 8; j++) b_reg[j] = Bs[k][tcol * 8 + j];
#pragma unroll
            for (int i = 0; i < 8; i++)
#pragma unroll
                for (int j = 0; j < 8; j++)
                    acc[i][j] += a_reg[i] * b_reg[j];
        }
        __syncthreads();
    }

#pragma unroll
    for (int i = 0; i < 8; i++) {
        int gRow = rowBase + trow * 8 + i;
        if (gRow >= M) continue;
#pragma unroll
        for (int j = 0; j < 8; j += 4) {
            float4 v = make_float4(acc[i][j], acc[i][j + 1], acc[i][j + 2], acc[i][j + 3]);
            if (bias != nullptr) {
                int c = tcol * 8 + j;
                v.x += bias[c]; v.y += bias[c + 1]; v.z += bias[c + 2]; v.w += bias[c + 3];
            }
            *(float4*)(C + (size_t)gRow * D + tcol * 8 + j) = v;
        }
    }
}

// ---------------------------------------------------------------------------
// Gate logits: glog[n][r] = dot(h[n], gw[r]); one warp per node.
// ---------------------------------------------------------------------------
__global__ void glog_kernel(const float* __restrict__ h, const float* __restrict__ gw,
                            int Nn)
{
    int warp = (int)((blockIdx.x * blockDim.x + threadIdx.x) >> 5);
    int lane = threadIdx.x & 31;
    if (warp >= Nn) return;
    float4 hv = ((const float4*)(h + (size_t)warp * D))[lane];
    float mine = 0.f;
#pragma unroll
    for (int r = 0; r < NRELS; r++) {
        float4 gv = ((const float4*)(gw + r * D))[lane];
        float dot = hv.x * gv.x + hv.y * gv.y + hv.z * gv.z + hv.w * gv.w;
#pragma unroll
        for (int off = 16; off > 0; off >>= 1)
            dot += __shfl_down_sync(0xffffffffu, dot, off);
        dot = __shfl_sync(0xffffffffu, dot, 0);
        if (lane == r) mine = dot;
    }
    if (lane < NRELS) g_glog[(size_t)warp * NRELS + lane] = mine;
}

// ---------------------------------------------------------------------------
// Edge scatter: one warp per edge. out[dst] += norm * sigmoid(glog) * hall[rel][src]
// ---------------------------------------------------------------------------
__global__ void edge_kernel(const int* __restrict__ src, const int* __restrict__ dst,
                            const int* __restrict__ rel, const float* __restrict__ norm,
                            float* __restrict__ out, int E, int Nn)
{
    int warp = (int)((blockIdx.x * blockDim.x + threadIdx.x) >> 5);
    int lane = threadIdx.x & 31;
    if (warp >= E) return;
    int s = src[warp];
    int dv = dst[warp];
    int r = rel[warp];
    float nm = norm[warp];
    float gl = g_glog[(size_t)s * NRELS + r];
    float g = nm / (1.f + expf(-gl));
    const float4 v = ((const float4*)(g_hall + ((size_t)r * Nn + s) * D))[lane];
    float* o = out + (size_t)dv * D + lane * 4;
    atomicAdd(o + 0, v.x * g);
    atomicAdd(o + 1, v.y * g);
    atomicAdd(o + 2, v.z * g);
    atomicAdd(o + 3, v.w * g);
}

__global__ void relu_kernel(float* __restrict__ x, size_t n)
{
    size_t i = (size_t)blockIdx.x * blockDim.x + threadIdx.x;
    if (i < n) x[i] = fmaxf(x[i], 0.f);
}

// ---------------------------------------------------------------------------
static void run_layer(const float* hin, const float* W, const float* bias,
                      const float* lw, const float* gw,
                      const int* src, const int* dst, const int* rel,
                      const float* norm, float* hall_ptr,
                      float* hout, int Nn, int E, bool apply_relu)
{
    int mblocks = (Nn + 127) / 128;

    // 1) h_all[r] = hin @ W[r]
    sgemm_kernel<<<dim3(mblocks, 1, NRELS), 256>>>(hin, W, hall_ptr, Nn, nullptr);
    // 2) gate logits
    int gwarps = Nn;
    glog_kernel<<<(gwarps * 32 + 255) / 256, 256>>>(hin, gw, Nn);
    // 3) out = hin @ loop_w + bias  (initializes accumulation target)
    sgemm_kernel<<<dim3(mblocks, 1, 1), 256>>>(hin, lw, hout, Nn, bias);
    // 4) edge scatter-accumulate
    edge_kernel<<<(E * 32 + 255) / 256, 256>>>(src, dst, rel, norm, hout, E, Nn);
    // 5) relu
    if (apply_relu) {
        size_t n = (size_t)Nn * D;
        relu_kernel<<<(int)((n + 255) / 256), 256>>>(hout, n);
    }
}

extern "C" void kernel_launch(void* const* d_in, const int* in_sizes, int n_in,
                              void* d_out, int out_size)
{
    const float* h    = (const float*)d_in[0];
    const float* norm = (const float*)d_in[1];
    const float* W0   = (const float*)d_in[2];
    const float* b0   = (const float*)d_in[3];
    const float* lw0  = (const float*)d_in[4];
    const float* gw0  = (const float*)d_in[5];
    const float* W1   = (const float*)d_in[6];
    const float* b1   = (const float*)d_in[7];
    const float* lw1  = (const float*)d_in[8];
    const float* gw1  = (const float*)d_in[9];
    const int*   src  = (const int*)d_in[10];
    const int*   dst  = (const int*)d_in[11];
    const int*   rel  = (const int*)d_in[12];
    float* out = (float*)d_out;

    int Nn = in_sizes[0] / D;      // 50000
    int E  = in_sizes[10];         // 800000

    float* hall_ptr = nullptr;
    float* h1_ptr = nullptr;
    cudaGetSymbolAddress((void**)&hall_ptr, g_hall);
    cudaGetSymbolAddress((void**)&h1_ptr, g_h1);

    // Layer 0: relu
    run_layer(h, W0, b0, lw0, gw0, src, dst, rel, norm, hall_ptr, h1_ptr, Nn, E, true);
    // Layer 1: no relu, writes final output
    run_layer(h1_ptr, W1, b1, lw1, gw1, src, dst, rel, norm, hall_ptr, out, Nn, E, false);
}

// round 2
// speedup vs baseline: 1.8464x; 1.8464x over previous
#include <cuda_runtime.h>
#include <math.h>
#include <stdint.h>

#define D 128
#define NRELS 16
#define MAXN 50000

// Scratch (allocation-free rule: __device__ globals)
__device__ float g_hall[(size_t)NRELS * MAXN * D];   // [r][n][d] transformed features
__device__ float g_glog[(size_t)MAXN * NRELS];       // [n][r] gate logits
__device__ float g_h1[(size_t)MAXN * D];             // layer-0 output

__device__ __forceinline__ uint32_t f2tf32(float x) {
    uint32_t y;
    asm("cvt.rna.tf32.f32 %0, %1;" : "=r"(y) : "f"(x));
    return y;
}

// ---------------------------------------------------------------------------
// tf32 tensor-core GEMM: C[z] = A @ B[z] (+bias). A:[M x 128], B[z]:[128 x 128]
// BM=128, BN=128, BK=16; 256 threads = 8 warps (2x4), warp tile 64x32,
// mma.sync.aligned.m16n8k8.row.col.f32.tf32.tf32.f32
// ---------------------------------------------------------------------------
#define BK 16
#define SMS 136   // smem row stride in words (128 + 8 pad -> conflict-free frags)

__global__ __launch_bounds__(256, 2)
void gemm_tf32(const float* __restrict__ A, const float* __restrict__ B0,
               float* __restrict__ C0, int M, const float* __restrict__ bias)
{
    const int z = blockIdx.z;
    const float* B = B0 + (size_t)z * D * D;
    float* C = C0 + (size_t)z * (size_t)M * D;

    __shared__ uint32_t As[BK][SMS];   // [k][m]
    __shared__ uint32_t Bs[BK][SMS];   // [k][n]

    const int tid  = threadIdx.x;
    const int lane = tid & 31;
    const int wid  = tid >> 5;
    const int warp_m = wid & 1;        // 2 warps along M (64 rows each)
    const int warp_n = wid >> 1;       // 4 warps along N (32 cols each)
    const int g = lane >> 2;           // group id 0..7
    const int c = lane & 3;            // thread in group 0..3

    const int mBase = blockIdx.x * 128;

    // A tile loader: thread -> row lm, k-halves lk (8 consecutive k)
    const int lm = tid & 127;
    const int lk = (tid >> 7) * 8;     // 0 or 8
    const int gRow = mBase + lm;
    const bool aValid = (gRow < M);
    const float* Aptr = A + (size_t)(aValid ? gRow : 0) * D;

    // B tile loader: row bk (0..15), 8 consecutive cols
    const int bk = tid >> 4;
    const int bn = (tid & 15) * 8;

    float acc[4][4][4];
#pragma unroll
    for (int mi = 0; mi < 4; mi++)
#pragma unroll
        for (int ni = 0; ni < 4; ni++)
#pragma unroll
            for (int f = 0; f < 4; f++) acc[mi][ni][f] = 0.f;

    for (int k0 = 0; k0 < D; k0 += BK) {
        float4 av0 = make_float4(0.f, 0.f, 0.f, 0.f), av1 = av0;
        if (aValid) {
            av0 = *(const float4*)(Aptr + k0 + lk);
            av1 = *(const float4*)(Aptr + k0 + lk + 4);
        }
        As[lk + 0][lm] = f2tf32(av0.x);
        As[lk + 1][lm] = f2tf32(av0.y);
        As[lk + 2][lm] = f2tf32(av0.z);
        As[lk + 3][lm] = f2tf32(av0.w);
        As[lk + 4][lm] = f2tf32(av1.x);
        As[lk + 5][lm] = f2tf32(av1.y);
        As[lk + 6][lm] = f2tf32(av1.z);
        As[lk + 7][lm] = f2tf32(av1.w);

        float4 bv0 = *(const float4*)(B + (size_t)(k0 + bk) * D + bn);
        float4 bv1 = *(const float4*)(B + (size_t)(k0 + bk) * D + bn + 4);
        Bs[bk][bn + 0] = f2tf32(bv0.x);
        Bs[bk][bn + 1] = f2tf32(bv0.y);
        Bs[bk][bn + 2] = f2tf32(bv0.z);
        Bs[bk][bn + 3] = f2tf32(bv0.w);
        Bs[bk][bn + 4] = f2tf32(bv1.x);
        Bs[bk][bn + 5] = f2tf32(bv1.y);
        Bs[bk][bn + 6] = f2tf32(bv1.z);
        Bs[bk][bn + 7] = f2tf32(bv1.w);
        __syncthreads();

#pragma unroll
        for (int ks = 0; ks < 2; ks++) {
            const int kb = ks * 8;
            uint32_t af[4][4], bf[4][2];
#pragma unroll
            for (int mi = 0; mi < 4; mi++) {
                const int m = warp_m * 64 + mi * 16;
                af[mi][0] = As[kb + c    ][m + g    ];
                af[mi][1] = As[kb + c    ][m + g + 8];
                af[mi][2] = As[kb + c + 4][m + g    ];
                af[mi][3] = As[kb + c + 4][m + g + 8];
            }
#pragma unroll
            for (int ni = 0; ni < 4; ni++) {
                const int n = warp_n * 32 + ni * 8;
                bf[ni][0] = Bs[kb + c    ][n + g];
                bf[ni][1] = Bs[kb + c + 4][n + g];
            }
#pragma unroll
            for (int mi = 0; mi < 4; mi++)
#pragma unroll
                for (int ni = 0; ni < 4; ni++) {
                    asm volatile(
                        "mma.sync.aligned.m16n8k8.row.col.f32.tf32.tf32.f32 "
                        "{%0,%1,%2,%3}, {%4,%5,%6,%7}, {%8,%9}, {%0,%1,%2,%3};\n"
                        : "+f"(acc[mi][ni][0]), "+f"(acc[mi][ni][1]),
                          "+f"(acc[mi][ni][2]), "+f"(acc[mi][ni][3])
                        : "r"(af[mi][0]), "r"(af[mi][1]),
                          "r"(af[mi][2]), "r"(af[mi][3]),
                          "r"(bf[ni][0]), "r"(bf[ni][1]));
                }
        }
        __syncthreads();
    }

    // Epilogue
#pragma unroll
    for (int mi = 0; mi < 4; mi++) {
        const int row0 = mBase + warp_m * 64 + mi * 16 + g;
        const int row1 = row0 + 8;
#pragma unroll
        for (int ni = 0; ni < 4; ni++) {
            const int col = warp_n * 32 + ni * 8 + c * 2;
            float bx = 0.f, by = 0.f;
            if (bias != nullptr) { bx = bias[col]; by = bias[col + 1]; }
            if (row0 < M) {
                float2 v = make_float2(acc[mi][ni][0] + bx, acc[mi][ni][1] + by);
                *(float2*)(C + (size_t)row0 * D + col) = v;
            }
            if (row1 < M) {
                float2 v = make_float2(acc[mi][ni][2] + bx, acc[mi][ni][3] + by);
                *(float2*)(C + (size_t)row1 * D + col) = v;
            }
        }
    }
}

// ---------------------------------------------------------------------------
// Gate logits: glog[n][r] = dot(h[n], gw[r]); one warp per node.
// ---------------------------------------------------------------------------
__global__ void glog_kernel(const float* __restrict__ h, const float* __restrict__ gw,
                            int Nn)
{
    int warp = (int)((blockIdx.x * blockDim.x + threadIdx.x) >> 5);
    int lane = threadIdx.x & 31;
    if (warp >= Nn) return;
    float4 hv = ((const float4*)(h + (size_t)warp * D))[lane];
    float mine = 0.f;
#pragma unroll
    for (int r = 0; r < NRELS; r++) {
        float4 gv = ((const float4*)(gw + r * D))[lane];
        float dot = hv.x * gv.x + hv.y * gv.y + hv.z * gv.z + hv.w * gv.w;
#pragma unroll
        for (int off = 16; off > 0; off >>= 1)
            dot += __shfl_down_sync(0xffffffffu, dot, off);
        dot = __shfl_sync(0xffffffffu, dot, 0);
        if (lane == r) mine = dot;
    }
    if (lane < NRELS) g_glog[(size_t)warp * NRELS + lane] = mine;
}

// ---------------------------------------------------------------------------
// Edge scatter: one warp per edge. out[dst] += norm*sigmoid(glog)*hall[rel][src]
// Uses vectorized red.global.add.v4.f32 (1 op per 16B instead of 4 scalars).
// ---------------------------------------------------------------------------
__global__ void edge_kernel(const int* __restrict__ src, const int* __restrict__ dst,
                            const int* __restrict__ rel, const float* __restrict__ norm,
                            float* __restrict__ out, int E, int Nn)
{
    int warp = (int)((blockIdx.x * blockDim.x + threadIdx.x) >> 5);
    int lane = threadIdx.x & 31;
    if (warp >= E) return;
    int s = src[warp];
    int dv = dst[warp];
    int r = rel[warp];
    float nm = norm[warp];
    float gl = g_glog[(size_t)s * NRELS + r];
    float g = nm / (1.f + expf(-gl));
    const float4 v = ((const float4*)(g_hall + ((size_t)r * Nn + s) * D))[lane];
    float* o = out + (size_t)dv * D + lane * 4;
    asm volatile("red.global.add.v4.f32 [%0], {%1,%2,%3,%4};"
                 :: "l"(o), "f"(v.x * g), "f"(v.y * g), "f"(v.z * g), "f"(v.w * g)
                 : "memory");
}

__global__ void relu_kernel(float* __restrict__ x, size_t n)
{
    size_t i = (size_t)blockIdx.x * blockDim.x + threadIdx.x;
    if (i < n) x[i] = fmaxf(x[i], 0.f);
}

// ---------------------------------------------------------------------------
static void run_layer(const float* hin, const float* W, const float* bias,
                      const float* lw, const float* gw,
                      const int* src, const int* dst, const int* rel,
                      const float* norm, float* hall_ptr,
                      float* hout, int Nn, int E, bool apply_relu)
{
    int mblocks = (Nn + 127) / 128;

    // 1) h_all[r] = hin @ W[r]   (tf32 tensor cores)
    gemm_tf32<<<dim3(mblocks, 1, NRELS), 256>>>(hin, W, hall_ptr, Nn, nullptr);
    // 2) gate logits
    glog_kernel<<<(Nn * 32 + 255) / 256, 256>>>(hin, gw, Nn);
    // 3) out = hin @ loop_w + bias  (initializes accumulation target)
    gemm_tf32<<<dim3(mblocks, 1, 1), 256>>>(hin, lw, hout, Nn, bias);
    // 4) edge scatter-accumulate
    edge_kernel<<<(E * 32 + 255) / 256, 256>>>(src, dst, rel, norm, hout, E, Nn);
    // 5) relu
    if (apply_relu) {
        size_t n = (size_t)Nn * D;
        relu_kernel<<<(int)((n + 255) / 256), 256>>>(hout, n);
    }
}

extern "C" void kernel_launch(void* const* d_in, const int* in_sizes, int n_in,
                              void* d_out, int out_size)
{
    const float* h    = (const float*)d_in[0];
    const float* norm = (const float*)d_in[1];
    const float* W0   = (const float*)d_in[2];
    const float* b0   = (const float*)d_in[3];
    const float* lw0  = (const float*)d_in[4];
    const float* gw0  = (const float*)d_in[5];
    const float* W1   = (const float*)d_in[6];
    const float* b1   = (const float*)d_in[7];
    const float* lw1  = (const float*)d_in[8];
    const float* gw1  = (const float*)d_in[9];
    const int*   src  = (const int*)d_in[10];
    const int*   dst  = (const int*)d_in[11];
    const int*   rel  = (const int*)d_in[12];
    float* out = (float*)d_out;

    int Nn = in_sizes[0] / D;      // 50000
    int E  = in_sizes[10];         // 800000

    float* hall_ptr = nullptr;
    float* h1_ptr = nullptr;
    cudaGetSymbolAddress((void**)&hall_ptr, g_hall);
    cudaGetSymbolAddress((void**)&h1_ptr, g_h1);

    // Layer 0: relu
    run_layer(h, W0, b0, lw0, gw0, src, dst, rel, norm, hall_ptr, h1_ptr, Nn, E, true);
    // Layer 1: no relu, writes final output
    run_layer(h1_ptr, W1, b1, lw1, gw1, src, dst, rel, norm, hall_ptr, out, Nn, E, false);
}

// round 4
// speedup vs baseline: 2.3833x; 1.2908x over previous
#include <cuda_runtime.h>
#include <math.h>
#include <stdint.h>

#define D 128
#define NRELS 16
#define MAXN 50000

// ---------------- scratch (__device__ globals: allocation-free rule) -------
__device__ float g_hall[(size_t)NRELS * MAXN * D];   // [r][n][d]
__device__ float g_glog[(size_t)MAXN * NRELS];       // [n][r]
__device__ float g_h1[(size_t)MAXN * D];             // layer-0 out
__device__ float g_atf[(size_t)MAXN * D];            // h rounded to tf32
__device__ float g_wt[(size_t)NRELS * D * D];        // W^T tf32-rounded [r][e][d]
__device__ float g_lwt[(size_t)D * D];               // loop_w^T tf32-rounded

__device__ __forceinline__ float f2tf32f(float x) {
    uint32_t y;
    asm("cvt.rna.tf32.f32 %0, %1;" : "=r"(y) : "f"(x));
    return __uint_as_float(y);
}
__device__ __forceinline__ uint32_t smem_u32(const void* p) {
    uint32_t a;
    asm("{ .reg .u64 t; cvta.to.shared.u64 t, %1; cvt.u32.u64 %0, t; }"
        : "=r"(a) : "l"(p));
    return a;
}
__device__ __forceinline__ void cp16(uint32_t dst, const void* src, int srcBytes) {
    asm volatile("cp.async.cg.shared.global [%0], [%1], 16, %2;"
                 :: "r"(dst), "l"(src), "r"(srcBytes) : "memory");
}
#define CP_COMMIT() asm volatile("cp.async.commit_group;" ::: "memory")
#define CP_WAIT0()  asm volatile("cp.async.wait_group 0;" ::: "memory")

// ---------------------------------------------------------------------------
// Relation-looped tf32 tensor-core GEMM.
//   C[r] = A @ B[r]  for r in [0, R), A:[M x 128] (tf32-prerounded fp32 bits),
//   B: [R][128 n][128 k] = W^T (tf32-prerounded). One CTA per 128-row tile;
//   A resident in SMEM; B double-buffered via cp.async.
// SMEM layout: rows of 128 words padded to 132 (conflict-free frag loads).
// ---------------------------------------------------------------------------
#define SROW 132
#define TILE_B (128 * SROW * 4)        // 67584 bytes

__global__ __launch_bounds__(256)
void gemm_rloop(const float* __restrict__ A, const float* __restrict__ B,
                float* __restrict__ C0, size_t strideC, int R, int M,
                const float* __restrict__ bias)
{
    extern __shared__ char smem[];
    const uint32_t sA  = smem_u32(smem);
    const uint32_t sB0 = sA + TILE_B;
    const uint32_t sB1 = sB0 + TILE_B;

    const int tid  = threadIdx.x;
    const int lane = tid & 31;
    const int wid  = tid >> 5;
    const int warp_m = wid & 1;         // 2 warps on M (64 rows each)
    const int warp_n = wid >> 1;        // 4 warps on N (32 cols each)
    const int g = lane >> 2;            // 0..7
    const int c = lane & 3;             // 0..3
    const int mBase = blockIdx.x * 128;

    // ---- prologue: A tile + B[0] via cp.async -----------------------------
    // 4096 chunks of 16B each (128 rows x 32 chunks), 16 per thread
#pragma unroll
    for (int it = 0; it < 16; it++) {
        int i = tid + it * 256;
        int row = i >> 5;
        int c4  = (i & 31) * 4;
        bool valid = (mBase + row) < M;
        const float* src = A + (valid ? ((size_t)(mBase + row) * D + c4) : 0);
        cp16(sA + (uint32_t)(row * SROW + c4) * 4, src, valid ? 16 : 0);
    }
#pragma unroll
    for (int it = 0; it < 16; it++) {
        int i = tid + it * 256;
        int row = i >> 5;
        int c4  = (i & 31) * 4;
        cp16(sB0 + (uint32_t)(row * SROW + c4) * 4,
             B + (size_t)row * D + c4, 16);
    }
    CP_COMMIT();
    CP_WAIT0();
    __syncthreads();

    const uint32_t aBase = sA + (uint32_t)(warp_m * 64) * SROW * 4;

    for (int r = 0; r < R; r++) {
        const uint32_t sCur = (r & 1) ? sB1 : sB0;
        const uint32_t sNxt = (r & 1) ? sB0 : sB1;

        if (r + 1 < R) {   // prefetch B[r+1] while computing with B[r]
            const float* Bn = B + (size_t)(r + 1) * D * D;
#pragma unroll
            for (int it = 0; it < 16; it++) {
                int i = tid + it * 256;
                int row = i >> 5;
                int c4  = (i & 31) * 4;
                cp16(sNxt + (uint32_t)(row * SROW + c4) * 4,
                     Bn + (size_t)row * D + c4, 16);
            }
            CP_COMMIT();
        }

        // ---- compute: 16 k-chunks of k8 -----------------------------------
        float acc[4][4][4];
#pragma unroll
        for (int mi = 0; mi < 4; mi++)
#pragma unroll
            for (int ni = 0; ni < 4; ni++)
#pragma unroll
                for (int f = 0; f < 4; f++) acc[mi][ni][f] = 0.f;

        const uint32_t bBase = sCur + (uint32_t)(warp_n * 32) * SROW * 4;

#pragma unroll
        for (int kc = 0; kc < 16; kc++) {
            const int kb = kc * 8;
            uint32_t af[4][4], bf[4][2];
#pragma unroll
            for (int mi = 0; mi < 4; mi++) {
                uint32_t a0 = aBase + (uint32_t)((mi * 16 + g) * SROW + kb + c) * 4;
                asm volatile("ld.shared.b32 %0, [%1];"     : "=r"(af[mi][0]) : "r"(a0));
                asm volatile("ld.shared.b32 %0, [%1+16];"  : "=r"(af[mi][2]) : "r"(a0));
                uint32_t a1 = a0 + 8u * SROW * 4u;
                asm volatile("ld.shared.b32 %0, [%1];"     : "=r"(af[mi][1]) : "r"(a1));
                asm volatile("ld.shared.b32 %0, [%1+16];"  : "=r"(af[mi][3]) : "r"(a1));
            }
#pragma unroll
            for (int ni = 0; ni < 4; ni++) {
                uint32_t b0 = bBase + (uint32_t)((ni * 8 + g) * SROW + kb + c) * 4;
                asm volatile("ld.shared.b32 %0, [%1];"     : "=r"(bf[ni][0]) : "r"(b0));
                asm volatile("ld.shared.b32 %0, [%1+16];"  : "=r"(bf[ni][1]) : "r"(b0));
            }
#pragma unroll
            for (int mi = 0; mi < 4; mi++)
#pragma unroll
                for (int ni = 0; ni < 4; ni++) {
                    asm volatile(
                        "mma.sync.aligned.m16n8k8.row.col.f32.tf32.tf32.f32 "
                        "{%0,%1,%2,%3}, {%4,%5,%6,%7}, {%8,%9}, {%0,%1,%2,%3};\n"
                        : "+f"(acc[mi][ni][0]), "+f"(acc[mi][ni][1]),
                          "+f"(acc[mi][ni][2]), "+f"(acc[mi][ni][3])
                        : "r"(af[mi][0]), "r"(af[mi][1]),
                          "r"(af[mi][2]), "r"(af[mi][3]),
                          "r"(bf[ni][0]), "r"(bf[ni][1]));
                }
        }

        // ---- epilogue: write C[r] ------------------------------------------
        float* C = C0 + (size_t)r * strideC;
#pragma unroll
        for (int mi = 0; mi < 4; mi++) {
            const int row0 = mBase + warp_m * 64 + mi * 16 + g;
            const int row1 = row0 + 8;
#pragma unroll
            for (int ni = 0; ni < 4; ni++) {
                const int col = warp_n * 32 + ni * 8 + c * 2;
                float bx = 0.f, by = 0.f;
                if (bias != nullptr) { bx = bias[col]; by = bias[col + 1]; }
                if (row0 < M)
                    *(float2*)(C + (size_t)row0 * D + col) =
                        make_float2(acc[mi][ni][0] + bx, acc[mi][ni][1] + by);
                if (row1 < M)
                    *(float2*)(C + (size_t)row1 * D + col) =
                        make_float2(acc[mi][ni][2] + bx, acc[mi][ni][3] + by);
            }
        }

        if (r + 1 < R) {
            CP_WAIT0();        // B[r+1] landed
            __syncthreads();   // and everyone is done reading sCur
        }
    }
}

// ---------------------------------------------------------------------------
// rounding kernels (fp32 -> tf32-rounded fp32 bits)
// ---------------------------------------------------------------------------
__global__ void round_kernel(const float* __restrict__ x, float* __restrict__ y,
                             size_t n)
{
    size_t i = (size_t)blockIdx.x * blockDim.x + threadIdx.x;
    if (i < n) y[i] = f2tf32f(x[i]);
}

// W[r][d][e] -> out[r][e][d], tf32-rounded
__global__ void round_wT_kernel(const float* __restrict__ W,
                                float* __restrict__ out, int R)
{
    int i = blockIdx.x * blockDim.x + threadIdx.x;
    if (i >= R * D * D) return;
    int r = i / (D * D);
    int e = (i / D) & (D - 1);
    int d = i & (D - 1);
    out[i] = f2tf32f(W[(size_t)r * D * D + (size_t)d * D + e]);
}

// ---------------------------------------------------------------------------
// gate logits: glog[n][r] = dot(h[n], gw[r]); one warp per node
// ---------------------------------------------------------------------------
__global__ void glog_kernel(const float* __restrict__ h, const float* __restrict__ gw,
                            int Nn)
{
    int warp = (int)((blockIdx.x * blockDim.x + threadIdx.x) >> 5);
    int lane = threadIdx.x & 31;
    if (warp >= Nn) return;
    float4 hv = ((const float4*)(h + (size_t)warp * D))[lane];
    float mine = 0.f;
#pragma unroll
    for (int r = 0; r < NRELS; r++) {
        float4 gv = ((const float4*)(gw + r * D))[lane];
        float dot = hv.x * gv.x + hv.y * gv.y + hv.z * gv.z + hv.w * gv.w;
#pragma unroll
        for (int off = 16; off > 0; off >>= 1)
            dot += __shfl_down_sync(0xffffffffu, dot, off);
        dot = __shfl_sync(0xffffffffu, dot, 0);
        if (lane == r) mine = dot;
    }
    if (lane < NRELS) g_glog[(size_t)warp * NRELS + lane] = mine;
}

// ---------------------------------------------------------------------------
// Edge scatter: 4 edges per warp (MLP=4); red.global.add.v4.f32
// ---------------------------------------------------------------------------
#define EPW 4
__global__ void edge_kernel(const int* __restrict__ src, const int* __restrict__ dst,
                            const int* __restrict__ rel, const float* __restrict__ norm,
                            float* __restrict__ out, int E, int Nn)
{
    int warp = (int)((blockIdx.x * blockDim.x + threadIdx.x) >> 5);
    int lane = threadIdx.x & 31;
    int base = warp * EPW;
    if (base >= E) return;

    float4 v[EPW];
    float g[EPW];
    int dv[EPW];
    int cnt = min(EPW, E - base);
#pragma unroll
    for (int i = 0; i < EPW; i++) {
        if (i >= cnt) break;
        int e = base + i;
        int s = __ldg(src + e);
        dv[i] = __ldg(dst + e);
        int r = __ldg(rel + e);
        float nm = __ldg(norm + e);
        float gl = g_glog[(size_t)s * NRELS + r];
        g[i] = nm / (1.f + expf(-gl));
        v[i] = ((const float4*)(g_hall + ((size_t)r * Nn + s) * D))[lane];
    }
#pragma unroll
    for (int i = 0; i < EPW; i++) {
        if (i >= cnt) break;
        float* o = out + (size_t)dv[i] * D + lane * 4;
        asm volatile("red.global.add.v4.f32 [%0], {%1,%2,%3,%4};"
                     :: "l"(o), "f"(v[i].x * g[i]), "f"(v[i].y * g[i]),
                        "f"(v[i].z * g[i]), "f"(v[i].w * g[i])
                     : "memory");
    }
}

__global__ void relu_kernel(float* __restrict__ x, size_t n)
{
    size_t i = (size_t)blockIdx.x * blockDim.x + threadIdx.x;
    if (i < n) x[i] = fmaxf(x[i], 0.f);
}

// ---------------------------------------------------------------------------
#define GEMM_SMEM (3 * TILE_B + 128)

static void run_layer(const float* hin, const float* W, const float* bias,
                      const float* lw, const float* gw,
                      const int* src, const int* dst, const int* rel,
                      const float* norm,
                      float* hall_ptr, float* hout,
                      float* atf, float* wt, float* lwt,
                      int Nn, int E, bool apply_relu)
{
    const int mtiles = (Nn + 127) / 128;
    const size_t nElem = (size_t)Nn * D;

    round_kernel<<<(int)((nElem + 255) / 256), 256>>>(hin, atf, nElem);
    round_wT_kernel<<<(NRELS * D * D + 255) / 256, 256>>>(W, wt, NRELS);
    round_wT_kernel<<<(D * D + 255) / 256, 256>>>(lw, lwt, 1);

    // hall[r] = h @ W[r]
    gemm_rloop<<<mtiles, 256, GEMM_SMEM>>>(atf, wt, hall_ptr,
                                           (size_t)Nn * D, NRELS, Nn, nullptr);
    // out = h @ loop_w + bias  (initializes accumulation target)
    gemm_rloop<<<mtiles, 256, GEMM_SMEM>>>(atf, lwt, hout, 0, 1, Nn, bias);

    glog_kernel<<<(Nn * 32 + 255) / 256, 256>>>(hin, gw, Nn);

    int warps = (E + EPW - 1) / EPW;
    edge_kernel<<<(warps * 32 + 255) / 256, 256>>>(src, dst, rel, norm, hout, E, Nn);

    if (apply_relu)
        relu_kernel<<<(int)((nElem + 255) / 256), 256>>>(hout, nElem);
}

extern "C" void kernel_launch(void* const* d_in, const int* in_sizes, int n_in,
                              void* d_out, int out_size)
{
    const float* h    = (const float*)d_in[0];
    const float* norm = (const float*)d_in[1];
    const float* W0   = (const float*)d_in[2];
    const float* b0   = (const float*)d_in[3];
    const float* lw0  = (const float*)d_in[4];
    const float* gw0  = (const float*)d_in[5];
    const float* W1   = (const float*)d_in[6];
    const float* b1   = (const float*)d_in[7];
    const float* lw1  = (const float*)d_in[8];
    const float* gw1  = (const float*)d_in[9];
    const int*   src  = (const int*)d_in[10];
    const int*   dst  = (const int*)d_in[11];
    const int*   rel  = (const int*)d_in[12];
    float* out = (float*)d_out;

    int Nn = in_sizes[0] / D;
    int E  = in_sizes[10];

    cudaFuncSetAttribute(gemm_rloop, cudaFuncAttributeMaxDynamicSharedMemorySize,
                         GEMM_SMEM);

    float *hall_ptr, *h1_ptr, *atf, *wt, *lwt;
    cudaGetSymbolAddress((void**)&hall_ptr, g_hall);
    cudaGetSymbolAddress((void**)&h1_ptr, g_h1);
    cudaGetSymbolAddress((void**)&atf, g_atf);
    cudaGetSymbolAddress((void**)&wt, g_wt);
    cudaGetSymbolAddress((void**)&lwt, g_lwt);

    run_layer(h, W0, b0, lw0, gw0, src, dst, rel, norm, hall_ptr, h1_ptr,
              atf, wt, lwt, Nn, E, true);
    run_layer(h1_ptr, W1, b1, lw1, gw1, src, dst, rel, norm, hall_ptr, out,
              atf, wt, lwt, Nn, E, false);
}

// round 5
// speedup vs baseline: 2.4101x; 1.0112x over previous
#include <cuda_runtime.h>
#include <math.h>
#include <stdint.h>

#define D 128
#define NRELS 16
#define MAXN 50000

// ---------------- scratch (__device__ globals: allocation-free rule) -------
__device__ float g_hall[(size_t)NRELS * MAXN * D];   // [r][n][d]
__device__ float g_glog[(size_t)MAXN * NRELS];       // [n][r]
__device__ float g_h1[(size_t)MAXN * D];             // layer-0 out
__device__ float g_atf[(size_t)MAXN * D];            // h rounded to tf32
__device__ float g_wt[(size_t)NRELS * D * D];        // W^T tf32-rounded [r][e][d]
__device__ float g_lwt[(size_t)D * D];               // loop_w^T tf32-rounded

__device__ __forceinline__ float f2tf32f(float x) {
    uint32_t y;
    asm("cvt.rna.tf32.f32 %0, %1;" : "=r"(y) : "f"(x));
    return __uint_as_float(y);
}
__device__ __forceinline__ uint32_t smem_u32(const void* p) {
    uint32_t a;
    asm("{ .reg .u64 t; cvta.to.shared.u64 t, %1; cvt.u32.u64 %0, t; }"
        : "=r"(a) : "l"(p));
    return a;
}
__device__ __forceinline__ void cp16(uint32_t dst, const void* src, int srcBytes) {
    asm volatile("cp.async.cg.shared.global [%0], [%1], 16, %2;"
                 :: "r"(dst), "l"(src), "r"(srcBytes) : "memory");
}
#define CP_COMMIT() asm volatile("cp.async.commit_group;" ::: "memory")
#define CP_WAIT0()  asm volatile("cp.async.wait_group 0;" ::: "memory")

// ---------------------------------------------------------------------------
// tf32 GEMM, 512 threads, BM=256, BN=128, warp tile 64x32 (16 warps: 4m x 4n).
// C[r] = A @ B[r] for r in [rBase, rBase+Rper). A resident in SMEM (full K),
// B streamed in K-half chunks (64 k) with cp.async double buffering so
// load(j+1) overlaps compute(j) continuously across the relation loop.
// ---------------------------------------------------------------------------
#define SROW_A 132
#define SROW_B 68
#define SM_A_BYTES (256 * SROW_A * 4)     // 135168
#define SM_BCHUNK  (128 * SROW_B * 4)     // 34816
#define GEMM_SMEM  (SM_A_BYTES + 2 * SM_BCHUNK)   // 204800

__global__ __launch_bounds__(512)
void gemm_v2(const float* __restrict__ A, const float* __restrict__ B,
             float* __restrict__ C0, size_t strideC, int Rper, int M,
             const float* __restrict__ bias)
{
    extern __shared__ char smem[];
    const uint32_t sA  = smem_u32(smem);
    const uint32_t sB0 = sA + SM_A_BYTES;
    const uint32_t sB1 = sB0 + SM_BCHUNK;

    const int tid  = threadIdx.x;
    const int lane = tid & 31;
    const int wid  = tid >> 5;
    const int warp_m = wid >> 2;        // 0..3 (64 rows each)
    const int warp_n = wid & 3;         // 0..3 (32 cols each)
    const int g = lane >> 2;            // 0..7
    const int c = lane & 3;             // 0..3
    const int mBase = blockIdx.x * 256;
    const int rBase = blockIdx.y * Rper;
    const int nChunks = 2 * Rper;

    // ---- stage A (256 x 128, full K) --------------------------------------
#pragma unroll
    for (int it = 0; it < 16; it++) {
        int i = tid + it * 512;
        int row = i >> 5;               // 0..255
        int c4  = (i & 31) * 4;
        bool valid = (mBase + row) < M;
        const float* src = A + (valid ? ((size_t)(mBase + row) * D + c4) : 0);
        cp16(sA + (uint32_t)(row * SROW_A + c4) * 4, src, valid ? 16 : 0);
    }
    // ---- stage B chunk 0 ---------------------------------------------------
    {
        const float* Bc = B + (size_t)rBase * D * D;   // half 0: cols 0..63
#pragma unroll
        for (int it = 0; it < 4; it++) {
            int i = tid + it * 512;
            int row = i >> 4;           // 0..127
            int c4  = (i & 15) * 4;     // 0..60
            cp16(sB0 + (uint32_t)(row * SROW_B + c4) * 4,
                 Bc + (size_t)row * D + c4, 16);
        }
    }
    CP_COMMIT();
    CP_WAIT0();
    __syncthreads();

    const uint32_t aBase = sA + (uint32_t)(warp_m * 64) * SROW_A * 4;

    float acc[4][4][4];

    for (int j = 0; j < nChunks; j++) {
        const uint32_t sCur = (j & 1) ? sB1 : sB0;

        // prefetch chunk j+1 (buffer (j+1)&1 was freed by the sync at end of j-1)
        if (j + 1 < nChunks) {
            const uint32_t sNxt = (j & 1) ? sB0 : sB1;
            const int r1 = rBase + ((j + 1) >> 1);
            const int h1 = ((j + 1) & 1) * 64;
            const float* Bc = B + (size_t)r1 * D * D + h1;
#pragma unroll
            for (int it = 0; it < 4; it++) {
                int i = tid + it * 512;
                int row = i >> 4;
                int c4  = (i & 15) * 4;
                cp16(sNxt + (uint32_t)(row * SROW_B + c4) * 4,
                     Bc + (size_t)row * D + c4, 16);
            }
            CP_COMMIT();
        }

        if (!(j & 1)) {   // new relation -> clear accumulators
#pragma unroll
            for (int mi = 0; mi < 4; mi++)
#pragma unroll
                for (int ni = 0; ni < 4; ni++)
#pragma unroll
                    for (int f = 0; f < 4; f++) acc[mi][ni][f] = 0.f;
        }

        // ---- compute 8 k8-steps against this chunk -------------------------
        const int kbGlob = (j & 1) * 64;
        const uint32_t bBase = sCur + (uint32_t)(warp_n * 32) * SROW_B * 4;
#pragma unroll
        for (int kc = 0; kc < 8; kc++) {
            const int kbA = kbGlob + kc * 8;
            const int kbB = kc * 8;
            uint32_t af[4][4], bf[4][2];
#pragma unroll
            for (int mi = 0; mi < 4; mi++) {
                uint32_t a0 = aBase + (uint32_t)((mi * 16 + g) * SROW_A + kbA + c) * 4;
                asm volatile("ld.shared.b32 %0, [%1];"    : "=r"(af[mi][0]) : "r"(a0));
                asm volatile("ld.shared.b32 %0, [%1+16];" : "=r"(af[mi][2]) : "r"(a0));
                uint32_t a1 = a0 + 8u * SROW_A * 4u;
                asm volatile("ld.shared.b32 %0, [%1];"    : "=r"(af[mi][1]) : "r"(a1));
                asm volatile("ld.shared.b32 %0, [%1+16];" : "=r"(af[mi][3]) : "r"(a1));
            }
#pragma unroll
            for (int ni = 0; ni < 4; ni++) {
                uint32_t b0 = bBase + (uint32_t)((ni * 8 + g) * SROW_B + kbB + c) * 4;
                asm volatile("ld.shared.b32 %0, [%1];"    : "=r"(bf[ni][0]) : "r"(b0));
                asm volatile("ld.shared.b32 %0, [%1+16];" : "=r"(bf[ni][1]) : "r"(b0));
            }
#pragma unroll
            for (int mi = 0; mi < 4; mi++)
#pragma unroll
                for (int ni = 0; ni < 4; ni++) {
                    asm volatile(
                        "mma.sync.aligned.m16n8k8.row.col.f32.tf32.tf32.f32 "
                        "{%0,%1,%2,%3}, {%4,%5,%6,%7}, {%8,%9}, {%0,%1,%2,%3};\n"
                        : "+f"(acc[mi][ni][0]), "+f"(acc[mi][ni][1]),
                          "+f"(acc[mi][ni][2]), "+f"(acc[mi][ni][3])
                        : "r"(af[mi][0]), "r"(af[mi][1]),
                          "r"(af[mi][2]), "r"(af[mi][3]),
                          "r"(bf[ni][0]), "r"(bf[ni][1]));
                }
        }

        if (j & 1) {   // relation complete -> epilogue (stores drain async)
            const int r = rBase + (j >> 1);
            float* C = C0 + (size_t)r * strideC;
#pragma unroll
            for (int mi = 0; mi < 4; mi++) {
                const int row0 = mBase + warp_m * 64 + mi * 16 + g;
                const int row1 = row0 + 8;
#pragma unroll
                for (int ni = 0; ni < 4; ni++) {
                    const int col = warp_n * 32 + ni * 8 + c * 2;
                    float bx = 0.f, by = 0.f;
                    if (bias != nullptr) { bx = bias[col]; by = bias[col + 1]; }
                    if (row0 < M)
                        *(float2*)(C + (size_t)row0 * D + col) =
                            make_float2(acc[mi][ni][0] + bx, acc[mi][ni][1] + by);
                    if (row1 < M)
                        *(float2*)(C + (size_t)row1 * D + col) =
                            make_float2(acc[mi][ni][2] + bx, acc[mi][ni][3] + by);
                }
            }
        }

        if (j + 1 < nChunks) {
            CP_WAIT0();        // chunk j+1 landed
            __syncthreads();   // all warps done with chunk j's buffer
        }
    }
}

// ---------------------------------------------------------------------------
// rounding kernels (fp32 -> tf32-rounded fp32 bits)
// ---------------------------------------------------------------------------
__global__ void round_kernel(const float* __restrict__ x, float* __restrict__ y,
                             size_t n)
{
    size_t i = (size_t)blockIdx.x * blockDim.x + threadIdx.x;
    if (i < n) y[i] = f2tf32f(x[i]);
}

// W[r][d][e] -> out[r][e][d], tf32-rounded
__global__ void round_wT_kernel(const float* __restrict__ W,
                                float* __restrict__ out, int R)
{
    int i = blockIdx.x * blockDim.x + threadIdx.x;
    if (i >= R * D * D) return;
    int r = i / (D * D);
    int e = (i / D) & (D - 1);
    int d = i & (D - 1);
    out[i] = f2tf32f(W[(size_t)r * D * D + (size_t)d * D + e]);
}

// ---------------------------------------------------------------------------
// gate logits: glog[n][r] = dot(h[n], gw[r]); one warp per node
// ---------------------------------------------------------------------------
__global__ void glog_kernel(const float* __restrict__ h, const float* __restrict__ gw,
                            int Nn)
{
    int warp = (int)((blockIdx.x * blockDim.x + threadIdx.x) >> 5);
    int lane = threadIdx.x & 31;
    if (warp >= Nn) return;
    float4 hv = ((const float4*)(h + (size_t)warp * D))[lane];
    float mine = 0.f;
#pragma unroll
    for (int r = 0; r < NRELS; r++) {
        float4 gv = ((const float4*)(gw + r * D))[lane];
        float dot = hv.x * gv.x + hv.y * gv.y + hv.z * gv.z + hv.w * gv.w;
#pragma unroll
        for (int off = 16; off > 0; off >>= 1)
            dot += __shfl_down_sync(0xffffffffu, dot, off);
        dot = __shfl_sync(0xffffffffu, dot, 0);
        if (lane == r) mine = dot;
    }
    if (lane < NRELS) g_glog[(size_t)warp * NRELS + lane] = mine;
}

// ---------------------------------------------------------------------------
// Edge scatter: 4 edges per warp (MLP=4); red.global.add.v4.f32
// ---------------------------------------------------------------------------
#define EPW 4
__global__ void edge_kernel(const int* __restrict__ src, const int* __restrict__ dst,
                            const int* __restrict__ rel, const float* __restrict__ norm,
                            float* __restrict__ out, int E, int Nn)
{
    int warp = (int)((blockIdx.x * blockDim.x + threadIdx.x) >> 5);
    int lane = threadIdx.x & 31;
    int base = warp * EPW;
    if (base >= E) return;

    float4 v[EPW];
    float g[EPW];
    int dv[EPW];
    int cnt = min(EPW, E - base);
#pragma unroll
    for (int i = 0; i < EPW; i++) {
        if (i >= cnt) break;
        int e = base + i;
        int s = __ldg(src + e);
        dv[i] = __ldg(dst + e);
        int r = __ldg(rel + e);
        float nm = __ldg(norm + e);
        float gl = g_glog[(size_t)s * NRELS + r];
        g[i] = nm / (1.f + expf(-gl));
        v[i] = ((const float4*)(g_hall + ((size_t)r * Nn + s) * D))[lane];
    }
#pragma unroll
    for (int i = 0; i < EPW; i++) {
        if (i >= cnt) break;
        float* o = out + (size_t)dv[i] * D + lane * 4;
        asm volatile("red.global.add.v4.f32 [%0], {%1,%2,%3,%4};"
                     :: "l"(o), "f"(v[i].x * g[i]), "f"(v[i].y * g[i]),
                        "f"(v[i].z * g[i]), "f"(v[i].w * g[i])
                     : "memory");
    }
}

__global__ void relu_kernel(float* __restrict__ x, size_t n)
{
    size_t i = (size_t)blockIdx.x * blockDim.x + threadIdx.x;
    if (i < n) x[i] = fmaxf(x[i], 0.f);
}

// ---------------------------------------------------------------------------
static void run_layer(const float* hin, const float* W, const float* bias,
                      const float* lw, const float* gw,
                      const int* src, const int* dst, const int* rel,
                      const float* norm,
                      float* hall_ptr, float* hout,
                      float* atf, float* wt, float* lwt,
                      int Nn, int E, bool apply_relu)
{
    const int mtiles = (Nn + 255) / 256;
    const size_t nElem = (size_t)Nn * D;

    round_kernel<<<(int)((nElem + 255) / 256), 256>>>(hin, atf, nElem);
    round_wT_kernel<<<(NRELS * D * D + 255) / 256, 256>>>(W, wt, NRELS);
    round_wT_kernel<<<(D * D + 255) / 256, 256>>>(lw, lwt, 1);

    // hall[r] = h @ W[r] : grid (mtiles, 2), 8 relations per CTA
    gemm_v2<<<dim3(mtiles, 2), 512, GEMM_SMEM>>>(atf, wt, hall_ptr,
                                                 (size_t)Nn * D, NRELS / 2, Nn,
                                                 nullptr);
    // out = h @ loop_w + bias
    gemm_v2<<<dim3(mtiles, 1), 512, GEMM_SMEM>>>(atf, lwt, hout, 0, 1, Nn, bias);

    glog_kernel<<<(Nn * 32 + 255) / 256, 256>>>(hin, gw, Nn);

    int warps = (E + EPW - 1) / EPW;
    edge_kernel<<<(warps * 32 + 255) / 256, 256>>>(src, dst, rel, norm, hout, E, Nn);

    if (apply_relu)
        relu_kernel<<<(int)((nElem + 255) / 256), 256>>>(hout, nElem);
}

extern "C" void kernel_launch(void* const* d_in, const int* in_sizes, int n_in,
                              void* d_out, int out_size)
{
    const float* h    = (const float*)d_in[0];
    const float* norm = (const float*)d_in[1];
    const float* W0   = (const float*)d_in[2];
    const float* b0   = (const float*)d_in[3];
    const float* lw0  = (const float*)d_in[4];
    const float* gw0  = (const float*)d_in[5];
    const float* W1   = (const float*)d_in[6];
    const float* b1   = (const float*)d_in[7];
    const float* lw1  = (const float*)d_in[8];
    const float* lw1b = nullptr; (void)lw1b;
    const float* gw1  = (const float*)d_in[9];
    const int*   src  = (const int*)d_in[10];
    const int*   dst  = (const int*)d_in[11];
    const int*   rel  = (const int*)d_in[12];
    float* out = (float*)d_out;

    int Nn = in_sizes[0] / D;
    int E  = in_sizes[10];

    cudaFuncSetAttribute(gemm_v2, cudaFuncAttributeMaxDynamicSharedMemorySize,
                         GEMM_SMEM);

    float *hall_ptr, *h1_ptr, *atf, *wt, *lwt;
    cudaGetSymbolAddress((void**)&hall_ptr, g_hall);
    cudaGetSymbolAddress((void**)&h1_ptr, g_h1);
    cudaGetSymbolAddress((void**)&atf, g_atf);
    cudaGetSymbolAddress((void**)&wt, g_wt);
    cudaGetSymbolAddress((void**)&lwt, g_lwt);

    run_layer(h, W0, b0, lw0, gw0, src, dst, rel, norm, hall_ptr, h1_ptr,
              atf, wt, lwt, Nn, E, true);
    run_layer(h1_ptr, W1, b1, lw1, gw1, src, dst, rel, norm, hall_ptr, out,
              atf, wt, lwt, Nn, E, false);
}